// round 13
// baseline (speedup 1.0000x reference)
#include <cuda_runtime.h>
#include <cuda_bf16.h>
#include <math.h>

typedef unsigned long long ull;

// ---------------- problem constants ----------------
#define N_TOK 65536
#define DSUB  8
#define KHEAD 256
#define KTAIL 64
#define EMBD  128
#define SUBD  16
#define SBLK  128           // stats x-blocks (per partition)
#define STAGES 4            // 128*4*128 = 65536 worst-case coverage
#define NSLOT (DSUB * SBLK) // 1024 partial slots
#define REDB  32            // slot-reduce blocks
#define SPB   (NSLOT / REDB)
#define TAU   3e-4f         // fast-path acceptance margin
#define CBLK  256           // compaction blocks (256 tokens each)
#define STATS_SMEM (2 * 128 * (SUBD + 2) * 8)              // 36864 B (2 d-groups)
#define ARGMX_SMEM (KHEAD * 8 * 8 + KHEAD * 16)            // cd 16KB + consts 4KB

// ---------------- device scratch (no allocs allowed) ----------------
__device__ int    g_cnt_h, g_cnt_t;
__device__ int    g_blkcnt[CBLK];
__device__ int    g_blkoff[CBLK];
__device__ int    g_head_list[N_TOK], g_tail_list[N_TOK];
__device__ double g_psum_h[NSLOT][KHEAD], g_pssq_h[NSLOT][KHEAD];
__device__ double g_psum_t[NSLOT][KTAIL], g_pssq_t[NSLOT][KTAIL];
__device__ double g_p2s_h[REDB][KHEAD], g_p2q_h[REDB][KHEAD];
__device__ double g_p2s_t[REDB][KTAIL], g_p2q_t[REDB][KTAIL];
__device__ double g_meand_h[KHEAD], g_ad_h[KHEAD];
__device__ double g_meand_t[KTAIL], g_ad_t[KTAIL];

// ---------------- packed f32x2 helpers ----------------
__device__ __forceinline__ ull pack2(float lo, float hi) {
    ull r; asm("mov.b64 %0, {%1,%2};" : "=l"(r) : "f"(lo), "f"(hi)); return r;
}
__device__ __forceinline__ void unpack2(ull v, float& lo, float& hi) {
    asm("mov.b64 {%0,%1}, %2;" : "=f"(lo), "=f"(hi) : "l"(v));
}
__device__ __forceinline__ ull add2(ull a, ull b) {
    ull r; asm("add.rn.f32x2 %0, %1, %2;" : "=l"(r) : "l"(a), "l"(b)); return r;
}
__device__ __forceinline__ ull mul2(ull a, ull b) {
    ull r; asm("mul.rn.f32x2 %0, %1, %2;" : "=l"(r) : "l"(a), "l"(b)); return r;
}
#define FMA2(acc, a, b) asm("fma.rn.f32x2 %0, %2, %3, %0;" : "+l"(acc) : "l"(acc), "l"(a), "l"(b))

// ---------------- deterministic compaction ----------------
__global__ void count_kernel(const int* __restrict__ part) {
    __shared__ int cnt;
    if (threadIdx.x == 0) cnt = 0;
    __syncthreads();
    int i = blockIdx.x * 256 + threadIdx.x;
    bool h = (part[i] == 0);
    unsigned hm = __ballot_sync(0xffffffffu, h);
    if ((threadIdx.x & 31) == 0) atomicAdd(&cnt, __popc(hm));
    __syncthreads();
    if (threadIdx.x == 0) g_blkcnt[blockIdx.x] = cnt;
}

__global__ void scan_kernel() {
    __shared__ int buf[CBLK];
    int t = threadIdx.x;
    buf[t] = g_blkcnt[t];
    __syncthreads();
    for (int off = 1; off < CBLK; off <<= 1) {
        int v = (t >= off) ? buf[t - off] : 0;
        __syncthreads();
        buf[t] += v;
        __syncthreads();
    }
    g_blkoff[t] = buf[t] - g_blkcnt[t];
    if (t == CBLK - 1) {
        g_cnt_h = buf[t];
        g_cnt_t = N_TOK - buf[t];
    }
}

__global__ void scatter_kernel(const int* __restrict__ part) {
    __shared__ int wcnt[8];
    int t = threadIdx.x;
    int lane = t & 31, w = t >> 5;
    int i = blockIdx.x * 256 + t;
    bool h = (part[i] == 0);
    unsigned hm = __ballot_sync(0xffffffffu, h);
    if (lane == 0) wcnt[w] = __popc(hm);
    __syncthreads();
    int wbase = 0;
    #pragma unroll
    for (int k = 0; k < 8; k++) wbase += (k < w) ? wcnt[k] : 0;
    int hrank = wbase + __popc(hm & ((1u << lane) - 1u));
    int hblk = g_blkoff[blockIdx.x];
    if (h) {
        g_head_list[hblk + hrank] = i;
    } else {
        int trank = t - hrank;
        int tblk = blockIdx.x * 256 - hblk;
        g_tail_list[tblk + trank] = i;
    }
}

// ---------------- head stats: 2 pairs/thread, 2 d per block ----------------
// FROZEN fp32 BITS (round-6 pattern) — do not touch. Measured 154us; both L1
// (60%) and occ (21%) subcritical; bit-freeze blocks further restructuring.
__device__ __forceinline__ void stats_head2(const int* __restrict__ inp,
                                            const float* __restrict__ emb,
                                            const float* __restrict__ cent,
                                            char* smraw) {
    if (blockIdx.y >= 4) return;              // uniform across block
    constexpr int G = 128;
    const int t = threadIdx.x;
    const int g = t >> 6;
    const int pt = t & 63;
    const int d = blockIdx.y * 2 + g;
    const int slot = d * SBLK + blockIdx.x;
    ull (*xbuf)[SUBD + 2] = reinterpret_cast<ull (*)[SUBD + 2]>(smraw) + (size_t)g * G;

    ull cA[SUBD], cB[SUBD];
    float nA0 = 0.f, nA1 = 0.f, nB0 = 0.f, nB1 = 0.f;
    {
        const float* pa0 = cent + ((size_t)d * KHEAD + pt) * SUBD;
        const float* pa1 = pa0 + 128 * SUBD;
        const float* pb0 = cent + ((size_t)d * KHEAD + pt + 64) * SUBD;
        const float* pb1 = pb0 + 128 * SUBD;
        #pragma unroll
        for (int s = 0; s < SUBD; s++) {
            float a = pa0[s], b = pa1[s];
            cA[s] = pack2(a, b);
            nA0 = __fadd_rn(nA0, __fmul_rn(a, a));
            nA1 = __fadd_rn(nA1, __fmul_rn(b, b));
            float c = pb0[s], e = pb1[s];
            cB[s] = pack2(c, e);
            nB0 = __fadd_rn(nB0, __fmul_rn(c, c));
            nB1 = __fadd_rn(nB1, __fmul_rn(e, e));
        }
    }
    const ull negn2A = pack2(-nA0, -nA1);
    const ull negn2B = pack2(-nB0, -nB1);
    const ull two2   = pack2(2.f, 2.f);

    const int cnt = g_cnt_h;
    const int* list = g_head_list;

    double dsA0 = 0, dsA1 = 0, dqA0 = 0, dqA1 = 0;
    double dsB0 = 0, dsB1 = 0, dqB0 = 0, dqB1 = 0;
    const int base = blockIdx.x * (STAGES * G);

    for (int st = 0; st < STAGES; ++st) {
        int sb = base + st * G;
        int nval = cnt - sb;
        if (nval <= 0) break;                 // uniform across block
        if (nval > G) nval = G;
        __syncthreads();
        #pragma unroll
        for (int rr = 0; rr < 2; rr++) {
            int row = pt + rr * 64;
            if (row < nval) {
                int tokr = list[sb + row];
                const float* xr = emb + (size_t)inp[tokr] * EMBD + d * SUBD;
                float n1 = 0.f;
                #pragma unroll
                for (int s = 0; s < SUBD; s++) {
                    float v = xr[s];
                    *((float2*)&xbuf[row][s]) = make_float2(v, v);
                    n1 = __fadd_rn(n1, __fmul_rn(v, v));
                }
                *((float2*)&xbuf[row][SUBD]) = make_float2(-n1, -n1);
            }
        }
        __syncthreads();

        ull sumA = 0ull, ssqA = 0ull, sumB = 0ull, ssqB = 0ull;
        for (int j = 0; j < nval; j++) {
            const ulonglong2* xr2 = (const ulonglong2*)&xbuf[j][0];
            ull a0 = 0ull, a1 = 0ull, a2 = 0ull, a3 = 0ull;
            ull b0 = 0ull, b1 = 0ull, b2 = 0ull, b3 = 0ull;
            #pragma unroll
            for (int q = 0; q < SUBD / 4; q++) {
                ulonglong2 xA = xr2[2 * q];        // scalars 4q, 4q+1
                ulonglong2 xB = xr2[2 * q + 1];    // scalars 4q+2, 4q+3
                FMA2(a0, xA.x, cA[4 * q]);
                FMA2(a1, xA.y, cA[4 * q + 1]);
                FMA2(a2, xB.x, cA[4 * q + 2]);
                FMA2(a3, xB.y, cA[4 * q + 3]);
                FMA2(b0, xA.x, cB[4 * q]);
                FMA2(b1, xA.y, cB[4 * q + 1]);
                FMA2(b2, xB.x, cB[4 * q + 2]);
                FMA2(b3, xB.y, cB[4 * q + 3]);
            }
            ull xn1 = xbuf[j][SUBD];
            ull dotA = add2(add2(a0, a1), add2(a2, a3));
            ull rA = mul2(dotA, two2);             // round-6 epilogue order
            rA = add2(rA, xn1);
            rA = add2(rA, negn2A);
            sumA = add2(sumA, rA);
            FMA2(ssqA, rA, rA);
            ull dotB = add2(add2(b0, b1), add2(b2, b3));
            ull rB = mul2(dotB, two2);
            rB = add2(rB, xn1);
            rB = add2(rB, negn2B);
            sumB = add2(sumB, rB);
            FMA2(ssqB, rB, rB);
        }
        float s0, s1, q0, q1;
        unpack2(sumA, s0, s1); unpack2(ssqA, q0, q1);
        dsA0 += (double)s0; dsA1 += (double)s1;
        dqA0 += (double)q0; dqA1 += (double)q1;
        unpack2(sumB, s0, s1); unpack2(ssqB, q0, q1);
        dsB0 += (double)s0; dsB1 += (double)s1;
        dqB0 += (double)q0; dqB1 += (double)q1;
    }

    g_psum_h[slot][pt]       = dsA0;
    g_psum_h[slot][pt + 128] = dsA1;
    g_psum_h[slot][pt + 64]  = dsB0;
    g_psum_h[slot][pt + 192] = dsB1;
    g_pssq_h[slot][pt]       = dqA0;
    g_pssq_h[slot][pt + 128] = dqA1;
    g_pssq_h[slot][pt + 64]  = dqB0;
    g_pssq_h[slot][pt + 192] = dqB1;
}

// ---------------- tail stats (unchanged round-6 structure, frozen) ----------
__device__ __forceinline__ void stats_tail(const int* __restrict__ inp,
                                           const float* __restrict__ emb,
                                           const float* __restrict__ cent,
                                           char* sm) {
    constexpr int NK = KTAIL;
    constexpr int NP = NK / 2;
    constexpr int G = 128;
    const int t = threadIdx.x;
    const int d = blockIdx.y;
    const int slot = d * SBLK + blockIdx.x;
    const int pairid = t & 31;
    const int rep = t >> 5;
    const int nrep = 4;

    ull (*xbuf)[SUBD + 2] = reinterpret_cast<ull (*)[SUBD + 2]>(sm);

    ull c2[SUBD];
    float n20 = 0.f, n21 = 0.f;
    {
        const float* p0 = cent + ((size_t)d * KHEAD + pairid) * SUBD;
        const float* p1 = p0 + (size_t)NP * SUBD;
        #pragma unroll
        for (int s = 0; s < SUBD; s++) {
            float a = p0[s], b = p1[s];
            c2[s] = pack2(a, b);
            n20 = __fadd_rn(n20, __fmul_rn(a, a));
            n21 = __fadd_rn(n21, __fmul_rn(b, b));
        }
    }
    const ull negn22 = pack2(-n20, -n21);
    const ull two2   = pack2(2.f, 2.f);

    const int cnt = g_cnt_t;
    const int* list = g_tail_list;

    double dsum0 = 0, dsum1 = 0, dssq0 = 0, dssq1 = 0;
    const int base = blockIdx.x * (STAGES * G);

    for (int st = 0; st < STAGES; ++st) {
        int sb = base + st * G;
        int nval = cnt - sb;
        if (nval <= 0) break;
        if (nval > G) nval = G;
        __syncthreads();
        if (t < nval) {
            int tok = list[sb + t];
            const float* xr = emb + (size_t)inp[tok] * EMBD + d * SUBD;
            float n1 = 0.f;
            #pragma unroll
            for (int s = 0; s < SUBD; s++) {
                float v = xr[s];
                *((float2*)&xbuf[t][s]) = make_float2(v, v);
                n1 = __fadd_rn(n1, __fmul_rn(v, v));
            }
            *((float2*)&xbuf[t][SUBD]) = make_float2(-n1, -n1);
        }
        __syncthreads();

        ull sum2 = 0ull, ssq2 = 0ull;
        for (int j = rep; j < nval; j += nrep) {
            const ulonglong2* xr2 = (const ulonglong2*)&xbuf[j][0];
            ull a0 = 0ull, a1 = 0ull, a2r = 0ull, a3 = 0ull;
            #pragma unroll
            for (int q = 0; q < SUBD / 4; q++) {
                ulonglong2 xA = xr2[2 * q];
                ulonglong2 xB = xr2[2 * q + 1];
                FMA2(a0,  xA.x, c2[4 * q]);
                FMA2(a1,  xA.y, c2[4 * q + 1]);
                FMA2(a2r, xB.x, c2[4 * q + 2]);
                FMA2(a3,  xB.y, c2[4 * q + 3]);
            }
            ull dot2 = add2(add2(a0, a1), add2(a2r, a3));
            ull r2 = mul2(dot2, two2);
            r2 = add2(r2, xbuf[j][SUBD]);
            r2 = add2(r2, negn22);
            sum2 = add2(sum2, r2);
            FMA2(ssq2, r2, r2);
        }
        float s0, s1, q0, q1;
        unpack2(sum2, s0, s1); unpack2(ssq2, q0, q1);
        dsum0 += (double)s0; dsum1 += (double)s1;
        dssq0 += (double)q0; dssq1 += (double)q1;
    }

    __syncthreads();
    double (*red)[4] = reinterpret_cast<double (*)[4]>(sm);
    red[t][0] = dsum0; red[t][1] = dsum1; red[t][2] = dssq0; red[t][3] = dssq1;
    __syncthreads();
    if (t < 32) {
        double r0 = 0, r1 = 0, r2d = 0, r3 = 0;
        #pragma unroll
        for (int r = 0; r < 4; r++) {
            r0  += red[t + 32 * r][0];
            r1  += red[t + 32 * r][1];
            r2d += red[t + 32 * r][2];
            r3  += red[t + 32 * r][3];
        }
        g_psum_t[slot][t]      = r0;
        g_psum_t[slot][t + 32] = r1;
        g_pssq_t[slot][t]      = r2d;
        g_pssq_t[slot][t + 32] = r3;
    }
}

__global__ __launch_bounds__(128) void stats_merged(const int* __restrict__ inp,
                                                    const float* __restrict__ emb,
                                                    const float* __restrict__ cent) {
    __shared__ __align__(16) char sm[STATS_SMEM];
    if (blockIdx.z == 0) stats_head2(inp, emb, cent, sm);
    else                 stats_tail(inp, emb, cent, sm);
}

// ---------------- two-stage deterministic slot reduce ----------------
__global__ void reduce_kernel() {
    int b = blockIdx.x, t = threadIdx.x;
    double s = 0.0, q = 0.0;
    for (int i = 0; i < SPB; i++) {
        s += g_psum_h[b * SPB + i][t];
        q += g_pssq_h[b * SPB + i][t];
    }
    g_p2s_h[b][t] = s; g_p2q_h[b][t] = q;
    if (t < KTAIL) {
        double s2 = 0.0, q2 = 0.0;
        for (int i = 0; i < SPB; i++) {
            s2 += g_psum_t[b * SPB + i][t];
            q2 += g_pssq_t[b * SPB + i][t];
        }
        g_p2s_t[b][t] = s2; g_p2q_t[b][t] = q2;
    }
}

__global__ void finalize_kernel() {
    int t = threadIdx.x;
    if (t < KHEAD) {
        double s = 0.0, q = 0.0;
        for (int i = 0; i < REDB; i++) { s += g_p2s_h[i][t]; q += g_p2q_h[i][t]; }
        double cnt = (double)g_cnt_h * 8.0; if (cnt < 1.0) cnt = 1.0;
        double m = s / cnt;
        double v = q / cnt - m * m;
        float vf = (float)v; if (!(vf > 0.f)) vf = 0.f;
        g_meand_h[t] = m;
        g_ad_h[t] = 1.0 / sqrt((double)(vf + 0.001f));
    } else if (t < KHEAD + KTAIL) {
        int k = t - KHEAD;
        double s = 0.0, q = 0.0;
        for (int i = 0; i < REDB; i++) { s += g_p2s_t[i][k]; q += g_p2q_t[i][k]; }
        double cnt = (double)g_cnt_t * 8.0; if (cnt < 1.0) cnt = 1.0;
        double m = s / cnt;
        double v = q / cnt - m * m;
        float vf = (float)v; if (!(vf > 0.f)) vf = 0.f;
        g_meand_t[k] = m;
        g_ad_t[k] = 1.0 / sqrt((double)(vf + 0.001f));
    }
}

// ---------------- argmax + output emit (4 tokens/thread, dim-paired) -------
// x packed as (x[s], x[s+8]) — no lane duplication (16 regs/token instead of
// 32). Centroids packed the same way; per-k consts (2a, a, e) in one float4.
// Per k: 5 LDS feed 4 tokens * (8 FMA2 dot + scalar affine). Fast path only —
// TAU-gated exact double slow path decides all borderline tokens, so this
// restructure cannot change any output.
template<int NK>
__device__ __forceinline__ void argmax_body(const int* __restrict__ inp,
                                            const float* __restrict__ emb,
                                            const float* __restrict__ cent,
                                            float* __restrict__ out,
                                            char* sm) {
    constexpr int TPT = 4;
    const int d = blockIdx.y;
    ull (*cd)[8]  = reinterpret_cast<ull (*)[8]>(sm);
    float4* csv   = reinterpret_cast<float4*>(sm + (size_t)NK * 8 * 8);

    const double* meand = (NK == 256) ? g_meand_h : g_meand_t;
    const double* ad    = (NK == 256) ? g_ad_h    : g_ad_t;

    for (int k = threadIdx.x; k < NK; k += blockDim.x) {
        const float* cp = cent + ((size_t)d * KHEAD + k) * SUBD;
        float cl[SUBD];
        double n2d = 0.0;
        #pragma unroll
        for (int s = 0; s < SUBD; s++) {
            cl[s] = cp[s];
            n2d += (double)cl[s] * (double)cl[s];
        }
        #pragma unroll
        for (int s = 0; s < 8; s++) cd[k][s] = pack2(cl[s], cl[s + 8]);
        double a = ad[k];
        float af = (float)a;
        float e  = (float)(-(n2d + meand[k]) * a);
        csv[k] = make_float4(2.f * af, af, e, 0.f);
    }
    __syncthreads();

    const int cnt = (NK == 256) ? g_cnt_h : g_cnt_t;
    const int* list = (NK == 256) ? g_head_list : g_tail_list;
    int ibase = (blockIdx.x * blockDim.x + threadIdx.x) * TPT;
    if (ibase >= cnt) return;
    const int rem = cnt - ibase;

    int tok[TPT];
    ull xp[TPT][8];
    float negn1[TPT];
    #pragma unroll
    for (int u = 0; u < TPT; u++) {
        int idx = ibase + u;
        tok[u] = list[(idx < cnt) ? idx : (cnt - 1)];
        const float* xr = emb + (size_t)inp[tok[u]] * EMBD + d * SUBD;
        float xs[SUBD];
        float n1 = 0.f;
        #pragma unroll
        for (int s = 0; s < SUBD; s++) {
            xs[s] = xr[s];
            n1 = __fadd_rn(n1, __fmul_rn(xs[s], xs[s]));
        }
        #pragma unroll
        for (int s = 0; s < 8; s++) xp[u][s] = pack2(xs[s], xs[s + 8]);
        negn1[u] = -n1;
    }

    float best[TPT], second[TPT];
    int bk[TPT];
    #pragma unroll
    for (int u = 0; u < TPT; u++) { best[u] = -3.4e38f; second[u] = -3.4e38f; bk[u] = 0; }

    #pragma unroll 2
    for (int k = 0; k < NK; k++) {
        const ulonglong2* crow = (const ulonglong2*)&cd[k][0];
        ulonglong2 c0 = crow[0], c1 = crow[1], c2v = crow[2], c3 = crow[3];
        float4 cv = csv[k];
        #pragma unroll
        for (int u = 0; u < TPT; u++) {
            ull a0 = 0ull, a1 = 0ull;
            FMA2(a0, xp[u][0], c0.x);  FMA2(a1, xp[u][1], c0.y);
            FMA2(a0, xp[u][2], c1.x);  FMA2(a1, xp[u][3], c1.y);
            FMA2(a0, xp[u][4], c2v.x); FMA2(a1, xp[u][5], c2v.y);
            FMA2(a0, xp[u][6], c3.x);  FMA2(a1, xp[u][7], c3.y);
            ull dd = add2(a0, a1);
            float lo, hi; unpack2(dd, lo, hi);
            float dotf = __fadd_rn(lo, hi);
            float sc = __fmaf_rn(cv.x, dotf, __fmaf_rn(cv.y, negn1[u], cv.z));
            if (sc > best[u]) { second[u] = best[u]; best[u] = sc; bk[u] = k; }
            else if (sc > second[u]) second[u] = sc;
        }
    }

    #pragma unroll
    for (int u = 0; u < TPT; u++) {
        if (u < rem) {
            int bku = bk[u];
            // Slow path: near-tie -> exact double argmax, lowest-k tie-break
            if (best[u] - second[u] <= TAU) {
                double n1d = 0.0;
                #pragma unroll
                for (int s = 0; s < 8; s++) {
                    float lo, hi; unpack2(xp[u][s], lo, hi);
                    n1d += (double)lo * (double)lo;
                    n1d += (double)hi * (double)hi;
                }
                const float* cdg = cent + (size_t)d * KHEAD * SUBD;
                double bestd = -1e300; bku = 0;
                for (int k = 0; k < NK; k++) {
                    const float* cp = cdg + k * SUBD;
                    double dot = 0.0, n2 = 0.0;
                    #pragma unroll
                    for (int s = 0; s < 8; s++) {
                        float lo, hi; unpack2(xp[u][s], lo, hi);
                        double cv0 = (double)cp[s];
                        double cv1 = (double)cp[s + 8];
                        dot += (double)lo * cv0;
                        dot += (double)hi * cv1;
                        n2  += cv0 * cv0;
                        n2  += cv1 * cv1;
                    }
                    double r = -n1d + 2.0 * dot - n2;
                    double v = (r - meand[k]) * ad[k];
                    if (v > bestd) { bestd = v; bku = k; }
                }
            }

            float ov[SUBD];
            #pragma unroll
            for (int s = 0; s < 8; s++) {
                float clo, chi; unpack2(cd[bku][s], clo, chi);
                float xlo, xhi; unpack2(xp[u][s], xlo, xhi);
                ov[s]     = __fadd_rn(__fsub_rn(clo, xlo), xlo);  // straight-through
                ov[s + 8] = __fadd_rn(__fsub_rn(chi, xhi), xhi);
            }
            float4* op = (float4*)(out + (size_t)tok[u] * EMBD + d * SUBD);
            #pragma unroll
            for (int q = 0; q < 4; q++)
                op[q] = make_float4(ov[4 * q], ov[4 * q + 1], ov[4 * q + 2], ov[4 * q + 3]);
        }
    }
}

// merged launch: z=0 -> head, z=1 -> tail
__global__ __launch_bounds__(128) void argmax_merged(const int* __restrict__ inp,
                                                     const float* __restrict__ emb,
                                                     const float* __restrict__ cent,
                                                     float* __restrict__ out) {
    __shared__ __align__(16) char sm[ARGMX_SMEM];
    if (blockIdx.z == 0) argmax_body<KHEAD>(inp, emb, cent, out, sm);
    else                 argmax_body<KTAIL>(inp, emb, cent, out, sm);
}

// ---------------- launch ----------------
extern "C" void kernel_launch(void* const* d_in, const int* in_sizes, int n_in,
                              void* d_out, int out_size) {
    const int*   inp  = (const int*)d_in[0];    // inputs (1024,64) int32
    const int*   part = (const int*)d_in[1];    // partitions (65536,) int32
    const float* emb  = (const float*)d_in[2];  // emb_table (100000,128) f32
    const float* cent = (const float*)d_in[3];  // centroids (8,256,16) f32
    float* out = (float*)d_out;

    count_kernel<<<CBLK, 256>>>(part);
    scan_kernel<<<1, 256>>>();
    scatter_kernel<<<CBLK, 256>>>(part);

    // z=0: head (y<4 used, 2 d per block); z=1: tail (y 0..7)
    stats_merged<<<dim3(SBLK, DSUB, 2), 128>>>(inp, emb, cent);

    reduce_kernel<<<REDB, 256>>>();
    finalize_kernel<<<1, 384>>>();

    // 4 tokens per thread: 128 x-blocks * 128 thr * 4 = 65536 worst-case
    argmax_merged<<<dim3(128, DSUB, 2), 128>>>(inp, emb, cent, out);
}

// round 14
// speedup vs baseline: 1.3800x; 1.3800x over previous
#include <cuda_runtime.h>
#include <cuda_bf16.h>
#include <math.h>

typedef unsigned long long ull;

// ---------------- problem constants ----------------
#define N_TOK 65536
#define DSUB  8
#define KHEAD 256
#define KTAIL 64
#define EMBD  128
#define SUBD  16
#define SBLK  128           // stats x-blocks (per partition)
#define STAGES 4            // 128*4*128 = 65536 worst-case coverage
#define NSLOT (DSUB * SBLK) // 1024 partial slots
#define REDB  32            // slot-reduce blocks
#define SPB   (NSLOT / REDB)
#define TAU   3e-4f         // fast-path acceptance margin
#define CBLK  256           // compaction blocks (256 tokens each)
#define STATS_SMEM (2 * 128 * (SUBD + 2) * 8)              // 36864 B (2 d-groups)
#define ARGMX_SMEM ((KHEAD/2) * SUBD * 8 + (KHEAD/2) * 32) // 20480 B
#define NDEC  (N_TOK * DSUB)

// ---------------- device scratch (no allocs allowed) ----------------
__device__ int    g_cnt_h, g_cnt_t;
__device__ int    g_blkcnt[CBLK];
__device__ int    g_blkoff[CBLK];
__device__ int    g_head_list[N_TOK], g_tail_list[N_TOK];
__device__ double g_psum_h[NSLOT][KHEAD], g_pssq_h[NSLOT][KHEAD];
__device__ double g_psum_t[NSLOT][KTAIL], g_pssq_t[NSLOT][KTAIL];
__device__ double g_p2s_h[REDB][KHEAD], g_p2q_h[REDB][KHEAD];
__device__ double g_p2s_t[REDB][KTAIL], g_p2q_t[REDB][KTAIL];
__device__ double g_meand_h[KHEAD], g_ad_h[KHEAD];
__device__ double g_meand_t[KTAIL], g_ad_t[KTAIL];
__device__ int    g_wcnt;            // borderline-decision worklist
__device__ int    g_wlist[NDEC];

// ---------------- packed f32x2 helpers ----------------
__device__ __forceinline__ ull pack2(float lo, float hi) {
    ull r; asm("mov.b64 %0, {%1,%2};" : "=l"(r) : "f"(lo), "f"(hi)); return r;
}
__device__ __forceinline__ void unpack2(ull v, float& lo, float& hi) {
    asm("mov.b64 {%0,%1}, %2;" : "=f"(lo), "=f"(hi) : "l"(v));
}
__device__ __forceinline__ ull add2(ull a, ull b) {
    ull r; asm("add.rn.f32x2 %0, %1, %2;" : "=l"(r) : "l"(a), "l"(b)); return r;
}
__device__ __forceinline__ ull mul2(ull a, ull b) {
    ull r; asm("mul.rn.f32x2 %0, %1, %2;" : "=l"(r) : "l"(a), "l"(b)); return r;
}
#define FMA2(acc, a, b) asm("fma.rn.f32x2 %0, %2, %3, %0;" : "+l"(acc) : "l"(acc), "l"(a), "l"(b))

// ---------------- deterministic compaction ----------------
__global__ void count_kernel(const int* __restrict__ part) {
    __shared__ int cnt;
    if (threadIdx.x == 0) cnt = 0;
    __syncthreads();
    int i = blockIdx.x * 256 + threadIdx.x;
    bool h = (part[i] == 0);
    unsigned hm = __ballot_sync(0xffffffffu, h);
    if ((threadIdx.x & 31) == 0) atomicAdd(&cnt, __popc(hm));
    __syncthreads();
    if (threadIdx.x == 0) g_blkcnt[blockIdx.x] = cnt;
}

__global__ void scan_kernel() {
    __shared__ int buf[CBLK];
    int t = threadIdx.x;
    buf[t] = g_blkcnt[t];
    __syncthreads();
    for (int off = 1; off < CBLK; off <<= 1) {
        int v = (t >= off) ? buf[t - off] : 0;
        __syncthreads();
        buf[t] += v;
        __syncthreads();
    }
    g_blkoff[t] = buf[t] - g_blkcnt[t];
    if (t == 0) g_wcnt = 0;
    if (t == CBLK - 1) {
        g_cnt_h = buf[t];
        g_cnt_t = N_TOK - buf[t];
    }
}

__global__ void scatter_kernel(const int* __restrict__ part) {
    __shared__ int wcnt[8];
    int t = threadIdx.x;
    int lane = t & 31, w = t >> 5;
    int i = blockIdx.x * 256 + t;
    bool h = (part[i] == 0);
    unsigned hm = __ballot_sync(0xffffffffu, h);
    if (lane == 0) wcnt[w] = __popc(hm);
    __syncthreads();
    int wbase = 0;
    #pragma unroll
    for (int k = 0; k < 8; k++) wbase += (k < w) ? wcnt[k] : 0;
    int hrank = wbase + __popc(hm & ((1u << lane) - 1u));
    int hblk = g_blkoff[blockIdx.x];
    if (h) {
        g_head_list[hblk + hrank] = i;
    } else {
        int trank = t - hrank;
        int tblk = blockIdx.x * 256 - hblk;
        g_tail_list[tblk + trank] = i;
    }
}

// ---------------- head stats: 2 pairs/thread, 2 d per block ----------------
// FROZEN fp32 BITS (round-6 pattern) — do not touch.
__device__ __forceinline__ void stats_head2(const int* __restrict__ inp,
                                            const float* __restrict__ emb,
                                            const float* __restrict__ cent,
                                            char* smraw) {
    if (blockIdx.y >= 4) return;              // uniform across block
    constexpr int G = 128;
    const int t = threadIdx.x;
    const int g = t >> 6;
    const int pt = t & 63;
    const int d = blockIdx.y * 2 + g;
    const int slot = d * SBLK + blockIdx.x;
    ull (*xbuf)[SUBD + 2] = reinterpret_cast<ull (*)[SUBD + 2]>(smraw) + (size_t)g * G;

    ull cA[SUBD], cB[SUBD];
    float nA0 = 0.f, nA1 = 0.f, nB0 = 0.f, nB1 = 0.f;
    {
        const float* pa0 = cent + ((size_t)d * KHEAD + pt) * SUBD;
        const float* pa1 = pa0 + 128 * SUBD;
        const float* pb0 = cent + ((size_t)d * KHEAD + pt + 64) * SUBD;
        const float* pb1 = pb0 + 128 * SUBD;
        #pragma unroll
        for (int s = 0; s < SUBD; s++) {
            float a = pa0[s], b = pa1[s];
            cA[s] = pack2(a, b);
            nA0 = __fadd_rn(nA0, __fmul_rn(a, a));
            nA1 = __fadd_rn(nA1, __fmul_rn(b, b));
            float c = pb0[s], e = pb1[s];
            cB[s] = pack2(c, e);
            nB0 = __fadd_rn(nB0, __fmul_rn(c, c));
            nB1 = __fadd_rn(nB1, __fmul_rn(e, e));
        }
    }
    const ull negn2A = pack2(-nA0, -nA1);
    const ull negn2B = pack2(-nB0, -nB1);
    const ull two2   = pack2(2.f, 2.f);

    const int cnt = g_cnt_h;
    const int* list = g_head_list;

    double dsA0 = 0, dsA1 = 0, dqA0 = 0, dqA1 = 0;
    double dsB0 = 0, dsB1 = 0, dqB0 = 0, dqB1 = 0;
    const int base = blockIdx.x * (STAGES * G);

    for (int st = 0; st < STAGES; ++st) {
        int sb = base + st * G;
        int nval = cnt - sb;
        if (nval <= 0) break;                 // uniform across block
        if (nval > G) nval = G;
        __syncthreads();
        #pragma unroll
        for (int rr = 0; rr < 2; rr++) {
            int row = pt + rr * 64;
            if (row < nval) {
                int tokr = list[sb + row];
                const float* xr = emb + (size_t)inp[tokr] * EMBD + d * SUBD;
                float n1 = 0.f;
                #pragma unroll
                for (int s = 0; s < SUBD; s++) {
                    float v = xr[s];
                    *((float2*)&xbuf[row][s]) = make_float2(v, v);
                    n1 = __fadd_rn(n1, __fmul_rn(v, v));
                }
                *((float2*)&xbuf[row][SUBD]) = make_float2(-n1, -n1);
            }
        }
        __syncthreads();

        ull sumA = 0ull, ssqA = 0ull, sumB = 0ull, ssqB = 0ull;
        for (int j = 0; j < nval; j++) {
            const ulonglong2* xr2 = (const ulonglong2*)&xbuf[j][0];
            ull a0 = 0ull, a1 = 0ull, a2 = 0ull, a3 = 0ull;
            ull b0 = 0ull, b1 = 0ull, b2 = 0ull, b3 = 0ull;
            #pragma unroll
            for (int q = 0; q < SUBD / 4; q++) {
                ulonglong2 xA = xr2[2 * q];        // scalars 4q, 4q+1
                ulonglong2 xB = xr2[2 * q + 1];    // scalars 4q+2, 4q+3
                FMA2(a0, xA.x, cA[4 * q]);
                FMA2(a1, xA.y, cA[4 * q + 1]);
                FMA2(a2, xB.x, cA[4 * q + 2]);
                FMA2(a3, xB.y, cA[4 * q + 3]);
                FMA2(b0, xA.x, cB[4 * q]);
                FMA2(b1, xA.y, cB[4 * q + 1]);
                FMA2(b2, xB.x, cB[4 * q + 2]);
                FMA2(b3, xB.y, cB[4 * q + 3]);
            }
            ull xn1 = xbuf[j][SUBD];
            ull dotA = add2(add2(a0, a1), add2(a2, a3));
            ull rA = mul2(dotA, two2);             // round-6 epilogue order
            rA = add2(rA, xn1);
            rA = add2(rA, negn2A);
            sumA = add2(sumA, rA);
            FMA2(ssqA, rA, rA);
            ull dotB = add2(add2(b0, b1), add2(b2, b3));
            ull rB = mul2(dotB, two2);
            rB = add2(rB, xn1);
            rB = add2(rB, negn2B);
            sumB = add2(sumB, rB);
            FMA2(ssqB, rB, rB);
        }
        float s0, s1, q0, q1;
        unpack2(sumA, s0, s1); unpack2(ssqA, q0, q1);
        dsA0 += (double)s0; dsA1 += (double)s1;
        dqA0 += (double)q0; dqA1 += (double)q1;
        unpack2(sumB, s0, s1); unpack2(ssqB, q0, q1);
        dsB0 += (double)s0; dsB1 += (double)s1;
        dqB0 += (double)q0; dqB1 += (double)q1;
    }

    g_psum_h[slot][pt]       = dsA0;
    g_psum_h[slot][pt + 128] = dsA1;
    g_psum_h[slot][pt + 64]  = dsB0;
    g_psum_h[slot][pt + 192] = dsB1;
    g_pssq_h[slot][pt]       = dqA0;
    g_pssq_h[slot][pt + 128] = dqA1;
    g_pssq_h[slot][pt + 64]  = dqB0;
    g_pssq_h[slot][pt + 192] = dqB1;
}

// ---------------- tail stats (unchanged round-6 structure, frozen) ----------
__device__ __forceinline__ void stats_tail(const int* __restrict__ inp,
                                           const float* __restrict__ emb,
                                           const float* __restrict__ cent,
                                           char* sm) {
    constexpr int NK = KTAIL;
    constexpr int NP = NK / 2;
    constexpr int G = 128;
    const int t = threadIdx.x;
    const int d = blockIdx.y;
    const int slot = d * SBLK + blockIdx.x;
    const int pairid = t & 31;
    const int rep = t >> 5;
    const int nrep = 4;

    ull (*xbuf)[SUBD + 2] = reinterpret_cast<ull (*)[SUBD + 2]>(sm);

    ull c2[SUBD];
    float n20 = 0.f, n21 = 0.f;
    {
        const float* p0 = cent + ((size_t)d * KHEAD + pairid) * SUBD;
        const float* p1 = p0 + (size_t)NP * SUBD;
        #pragma unroll
        for (int s = 0; s < SUBD; s++) {
            float a = p0[s], b = p1[s];
            c2[s] = pack2(a, b);
            n20 = __fadd_rn(n20, __fmul_rn(a, a));
            n21 = __fadd_rn(n21, __fmul_rn(b, b));
        }
    }
    const ull negn22 = pack2(-n20, -n21);
    const ull two2   = pack2(2.f, 2.f);

    const int cnt = g_cnt_t;
    const int* list = g_tail_list;

    double dsum0 = 0, dsum1 = 0, dssq0 = 0, dssq1 = 0;
    const int base = blockIdx.x * (STAGES * G);

    for (int st = 0; st < STAGES; ++st) {
        int sb = base + st * G;
        int nval = cnt - sb;
        if (nval <= 0) break;
        if (nval > G) nval = G;
        __syncthreads();
        if (t < nval) {
            int tok = list[sb + t];
            const float* xr = emb + (size_t)inp[tok] * EMBD + d * SUBD;
            float n1 = 0.f;
            #pragma unroll
            for (int s = 0; s < SUBD; s++) {
                float v = xr[s];
                *((float2*)&xbuf[t][s]) = make_float2(v, v);
                n1 = __fadd_rn(n1, __fmul_rn(v, v));
            }
            *((float2*)&xbuf[t][SUBD]) = make_float2(-n1, -n1);
        }
        __syncthreads();

        ull sum2 = 0ull, ssq2 = 0ull;
        for (int j = rep; j < nval; j += nrep) {
            const ulonglong2* xr2 = (const ulonglong2*)&xbuf[j][0];
            ull a0 = 0ull, a1 = 0ull, a2r = 0ull, a3 = 0ull;
            #pragma unroll
            for (int q = 0; q < SUBD / 4; q++) {
                ulonglong2 xA = xr2[2 * q];
                ulonglong2 xB = xr2[2 * q + 1];
                FMA2(a0,  xA.x, c2[4 * q]);
                FMA2(a1,  xA.y, c2[4 * q + 1]);
                FMA2(a2r, xB.x, c2[4 * q + 2]);
                FMA2(a3,  xB.y, c2[4 * q + 3]);
            }
            ull dot2 = add2(add2(a0, a1), add2(a2r, a3));
            ull r2 = mul2(dot2, two2);
            r2 = add2(r2, xbuf[j][SUBD]);
            r2 = add2(r2, negn22);
            sum2 = add2(sum2, r2);
            FMA2(ssq2, r2, r2);
        }
        float s0, s1, q0, q1;
        unpack2(sum2, s0, s1); unpack2(ssq2, q0, q1);
        dsum0 += (double)s0; dsum1 += (double)s1;
        dssq0 += (double)q0; dssq1 += (double)q1;
    }

    __syncthreads();
    double (*red)[4] = reinterpret_cast<double (*)[4]>(sm);
    red[t][0] = dsum0; red[t][1] = dsum1; red[t][2] = dssq0; red[t][3] = dssq1;
    __syncthreads();
    if (t < 32) {
        double r0 = 0, r1 = 0, r2d = 0, r3 = 0;
        #pragma unroll
        for (int r = 0; r < 4; r++) {
            r0  += red[t + 32 * r][0];
            r1  += red[t + 32 * r][1];
            r2d += red[t + 32 * r][2];
            r3  += red[t + 32 * r][3];
        }
        g_psum_t[slot][t]      = r0;
        g_psum_t[slot][t + 32] = r1;
        g_pssq_t[slot][t]      = r2d;
        g_pssq_t[slot][t + 32] = r3;
    }
}

__global__ __launch_bounds__(128) void stats_merged(const int* __restrict__ inp,
                                                    const float* __restrict__ emb,
                                                    const float* __restrict__ cent) {
    __shared__ __align__(16) char sm[STATS_SMEM];
    if (blockIdx.z == 0) stats_head2(inp, emb, cent, sm);
    else                 stats_tail(inp, emb, cent, sm);
}

// ---------------- two-stage deterministic slot reduce ----------------
__global__ void reduce_kernel() {
    int b = blockIdx.x, t = threadIdx.x;
    double s = 0.0, q = 0.0;
    for (int i = 0; i < SPB; i++) {
        s += g_psum_h[b * SPB + i][t];
        q += g_pssq_h[b * SPB + i][t];
    }
    g_p2s_h[b][t] = s; g_p2q_h[b][t] = q;
    if (t < KTAIL) {
        double s2 = 0.0, q2 = 0.0;
        for (int i = 0; i < SPB; i++) {
            s2 += g_psum_t[b * SPB + i][t];
            q2 += g_pssq_t[b * SPB + i][t];
        }
        g_p2s_t[b][t] = s2; g_p2q_t[b][t] = q2;
    }
}

__global__ void finalize_kernel() {
    int t = threadIdx.x;
    if (t < KHEAD) {
        double s = 0.0, q = 0.0;
        for (int i = 0; i < REDB; i++) { s += g_p2s_h[i][t]; q += g_p2q_h[i][t]; }
        double cnt = (double)g_cnt_h * 8.0; if (cnt < 1.0) cnt = 1.0;
        double m = s / cnt;
        double v = q / cnt - m * m;
        float vf = (float)v; if (!(vf > 0.f)) vf = 0.f;
        g_meand_h[t] = m;
        g_ad_h[t] = 1.0 / sqrt((double)(vf + 0.001f));
    } else if (t < KHEAD + KTAIL) {
        int k = t - KHEAD;
        double s = 0.0, q = 0.0;
        for (int i = 0; i < REDB; i++) { s += g_p2s_t[i][k]; q += g_p2q_t[i][k]; }
        double cnt = (double)g_cnt_t * 8.0; if (cnt < 1.0) cnt = 1.0;
        double m = s / cnt;
        double v = q / cnt - m * m;
        float vf = (float)v; if (!(vf > 0.f)) vf = 0.f;
        g_meand_t[k] = m;
        g_ad_t[k] = 1.0 / sqrt((double)(vf + 0.001f));
    }
}

// ---------------- argmax hot kernel (2 tokens/thread, round-12 math) -------
// Borderline decisions (margin <= TAU) push (tok,d,partition) onto a worklist
// for the exact fixup kernel and emit the fast winner as a placeholder. No
// double math in this kernel -> lower register pressure, higher occupancy.
template<int NK>
__device__ __forceinline__ void argmax_body(const int* __restrict__ inp,
                                            const float* __restrict__ emb,
                                            const float* __restrict__ cent,
                                            float* __restrict__ out,
                                            char* sm) {
    constexpr int NP = NK / 2;
    const int d = blockIdx.y;
    ull (*c2s)[SUBD] = reinterpret_cast<ull (*)[SUBD]>(sm);
    ull (*cst)[4]    = reinterpret_cast<ull (*)[4]>(sm + (size_t)NP * SUBD * 8);

    const double* meand = (NK == 256) ? g_meand_h : g_meand_t;
    const double* ad    = (NK == 256) ? g_ad_h    : g_ad_t;

    for (int j = threadIdx.x; j < NP; j += blockDim.x) {
        const float* p0 = cent + ((size_t)d * KHEAD + j) * SUBD;
        const float* p1 = p0 + (size_t)NP * SUBD;
        double n2d0 = 0.0, n2d1 = 0.0;
        #pragma unroll
        for (int s = 0; s < SUBD; s++) {
            float a = p0[s], b = p1[s];
            c2s[j][s] = pack2(a, b);
            n2d0 += (double)a * (double)a;
            n2d1 += (double)b * (double)b;
        }
        double a0 = ad[j], a1 = ad[j + NP];
        float af0 = (float)a0, af1 = (float)a1;
        float e0 = (float)(-(n2d0 + meand[j]) * a0);
        float e1 = (float)(-(n2d1 + meand[j + NP]) * a1);
        cst[j][0] = pack2(2.f * af0, 2.f * af1);
        cst[j][1] = pack2(af0, af1);
        cst[j][2] = pack2(e0, e1);
    }
    __syncthreads();

    const int cnt = (NK == 256) ? g_cnt_h : g_cnt_t;
    const int* list = (NK == 256) ? g_head_list : g_tail_list;
    int ibase = (blockIdx.x * blockDim.x + threadIdx.x) * 2;
    if (ibase >= cnt) return;
    const int ntk = (ibase + 1 < cnt) ? 2 : 1;

    int tok[2];
    tok[0] = list[ibase];
    tok[1] = (ntk == 2) ? list[ibase + 1] : tok[0];
    ull xd[2][SUBD], negn1[2];
    #pragma unroll
    for (int u = 0; u < 2; u++) {
        const float* xr = emb + (size_t)inp[tok[u]] * EMBD + d * SUBD;
        float n1 = 0.f;
        #pragma unroll
        for (int s = 0; s < SUBD; s++) {
            float v = xr[s];
            n1 = __fadd_rn(n1, __fmul_rn(v, v));
            xd[u][s] = pack2(v, v);
        }
        negn1[u] = pack2(-n1, -n1);
    }

    float best[2] = {-3.4e38f, -3.4e38f};
    float second[2] = {-3.4e38f, -3.4e38f};
    int bk[2] = {0, 0};
    for (int j = 0; j < NP; j++) {
        const ulonglong2* crow = (const ulonglong2*)&c2s[j][0];
        ulonglong2 kc = ((const ulonglong2*)&cst[j][0])[0];   // (twoa2, a2)
        ull e2 = cst[j][2];
        ull a0 = 0ull, a1 = 0ull, b0 = 0ull, b1 = 0ull;
        #pragma unroll
        for (int q = 0; q < SUBD / 2; q++) {
            ulonglong2 cA = crow[q];
            FMA2(a0, xd[0][2 * q],     cA.x);
            FMA2(a1, xd[0][2 * q + 1], cA.y);
            FMA2(b0, xd[1][2 * q],     cA.x);
            FMA2(b1, xd[1][2 * q + 1], cA.y);
        }
        ull dA = add2(a0, a1);
        ull tA = e2;
        FMA2(tA, kc.y, negn1[0]);
        FMA2(tA, kc.x, dA);
        ull dB = add2(b0, b1);
        ull tB = e2;
        FMA2(tB, kc.y, negn1[1]);
        FMA2(tB, kc.x, dB);
        float s0, s1;
        unpack2(tA, s0, s1);
        if (s0 > best[0]) { second[0] = best[0]; best[0] = s0; bk[0] = j; }
        else if (s0 > second[0]) second[0] = s0;
        if (s1 > best[0]) { second[0] = best[0]; best[0] = s1; bk[0] = j + NP; }
        else if (s1 > second[0]) second[0] = s1;
        unpack2(tB, s0, s1);
        if (s0 > best[1]) { second[1] = best[1]; best[1] = s0; bk[1] = j; }
        else if (s0 > second[1]) second[1] = s0;
        if (s1 > best[1]) { second[1] = best[1]; best[1] = s1; bk[1] = j + NP; }
        else if (s1 > second[1]) second[1] = s1;
    }

    #pragma unroll
    for (int u = 0; u < 2; u++) {
        if (u < ntk) {
            // Borderline -> defer exact decision to fixup kernel
            if (best[u] - second[u] <= TAU) {
                int w = atomicAdd(&g_wcnt, 1);
                g_wlist[w] = (tok[u] << 4) | (d << 1) | ((NK == 256) ? 0 : 1);
            }
            int jj = (bk[u] < NP) ? bk[u] : (bk[u] - NP);
            bool hi_half = (bk[u] >= NP);
            float ov[SUBD];
            #pragma unroll
            for (int s = 0; s < SUBD; s++) {
                float lo, hf; unpack2(c2s[jj][s], lo, hf);
                float cv = hi_half ? hf : lo;
                float xlo, xhi; unpack2(xd[u][s], xlo, xhi);
                ov[s] = __fadd_rn(__fsub_rn(cv, xlo), xlo);  // straight-through
            }
            float4* op = (float4*)(out + (size_t)tok[u] * EMBD + d * SUBD);
            #pragma unroll
            for (int q = 0; q < 4; q++)
                op[q] = make_float4(ov[4 * q], ov[4 * q + 1], ov[4 * q + 2], ov[4 * q + 3]);
        }
    }
}

// merged launch: z=0 -> head, z=1 -> tail
__global__ __launch_bounds__(128) void argmax_merged(const int* __restrict__ inp,
                                                     const float* __restrict__ emb,
                                                     const float* __restrict__ cent,
                                                     float* __restrict__ out) {
    __shared__ __align__(16) char sm[ARGMX_SMEM];
    if (blockIdx.z == 0) argmax_body<KHEAD>(inp, emb, cent, out, sm);
    else                 argmax_body<KTAIL>(inp, emb, cent, out, sm);
}

// ---------------- exact fixup (bit-identical to the old inline slow path) --
// Each entry independent & exact (ascending s/k, strict >, lowest-k ties) ->
// worklist order irrelevant -> output deterministic.
__global__ void fixup_kernel(const int* __restrict__ inp,
                             const float* __restrict__ emb,
                             const float* __restrict__ cent,
                             float* __restrict__ out) {
    int total = g_wcnt;
    for (int w = blockIdx.x * blockDim.x + threadIdx.x; w < total;
         w += gridDim.x * blockDim.x) {
        int e = g_wlist[w];
        int tok = e >> 4;
        int d = (e >> 1) & 7;
        int tail = e & 1;
        int NK = tail ? KTAIL : KHEAD;
        const double* meand = tail ? g_meand_t : g_meand_h;
        const double* ad    = tail ? g_ad_t    : g_ad_h;

        const float* xr = emb + (size_t)inp[tok] * EMBD + d * SUBD;
        float xs[SUBD];
        double n1d = 0.0;
        #pragma unroll
        for (int s = 0; s < SUBD; s++) {
            xs[s] = xr[s];
            n1d += (double)xs[s] * (double)xs[s];
        }
        const float* cd = cent + (size_t)d * KHEAD * SUBD;
        double bestd = -1e300; int bk = 0;
        for (int k = 0; k < NK; k++) {
            const float* cp = cd + k * SUBD;
            double dot = 0.0, n2 = 0.0;
            #pragma unroll
            for (int s = 0; s < SUBD; s++) {
                double cv = (double)cp[s];
                dot += (double)xs[s] * cv;
                n2  += cv * cv;
            }
            double r = -n1d + 2.0 * dot - n2;
            double v = (r - meand[k]) * ad[k];
            if (v > bestd) { bestd = v; bk = k; }
        }

        const float* cp = cd + bk * SUBD;
        float ov[SUBD];
        #pragma unroll
        for (int s = 0; s < SUBD; s++)
            ov[s] = __fadd_rn(__fsub_rn(cp[s], xs[s]), xs[s]);
        float4* op = (float4*)(out + (size_t)tok * EMBD + d * SUBD);
        #pragma unroll
        for (int q = 0; q < 4; q++)
            op[q] = make_float4(ov[4 * q], ov[4 * q + 1], ov[4 * q + 2], ov[4 * q + 3]);
    }
}

// ---------------- launch ----------------
extern "C" void kernel_launch(void* const* d_in, const int* in_sizes, int n_in,
                              void* d_out, int out_size) {
    const int*   inp  = (const int*)d_in[0];    // inputs (1024,64) int32
    const int*   part = (const int*)d_in[1];    // partitions (65536,) int32
    const float* emb  = (const float*)d_in[2];  // emb_table (100000,128) f32
    const float* cent = (const float*)d_in[3];  // centroids (8,256,16) f32
    float* out = (float*)d_out;

    count_kernel<<<CBLK, 256>>>(part);
    scan_kernel<<<1, 256>>>();                  // also zeroes g_wcnt
    scatter_kernel<<<CBLK, 256>>>(part);

    // z=0: head (y<4 used, 2 d per block); z=1: tail (y 0..7)
    stats_merged<<<dim3(SBLK, DSUB, 2), 128>>>(inp, emb, cent);

    reduce_kernel<<<REDB, 256>>>();
    finalize_kernel<<<1, 384>>>();

    // 2 tokens per thread: 256 x-blocks * 128 thr * 2 = 65536 worst-case
    argmax_merged<<<dim3(256, DSUB, 2), 128>>>(inp, emb, cent, out);
    fixup_kernel<<<128, 128>>>(inp, emb, cent, out);
}

// round 15
// speedup vs baseline: 1.4129x; 1.0239x over previous
#include <cuda_runtime.h>
#include <cuda_bf16.h>
#include <math.h>

typedef unsigned long long ull;

// ---------------- problem constants ----------------
#define N_TOK 65536
#define DSUB  8
#define KHEAD 256
#define KTAIL 64
#define EMBD  128
#define SUBD  16
#define SBLK  128           // stats x-blocks (per partition)
#define STAGES 4            // 128*4*128 = 65536 worst-case coverage
#define NSLOT (DSUB * SBLK) // 1024 partial slots
#define REDB  32            // slot-reduce blocks
#define SPB   (NSLOT / REDB)
#define TAU   3e-4f         // fast-path acceptance margin
#define CBLK  256           // compaction blocks (256 tokens each)
#define STATS_SMEM (2 * 128 * (SUBD + 2) * 8)              // 36864 B (2 d-groups)
#define ARGMX_SMEM ((KHEAD/2) * SUBD * 8 + (KHEAD/2) * 32) // 20480 B
#define NDEC  (N_TOK * DSUB)

// ---------------- device scratch (no allocs allowed) ----------------
__device__ int    g_cnt_h, g_cnt_t;
__device__ int    g_blkcnt[CBLK];
__device__ int    g_blkoff[CBLK];
__device__ int    g_head_list[N_TOK], g_tail_list[N_TOK];
__device__ double g_psum_h[NSLOT][KHEAD], g_pssq_h[NSLOT][KHEAD];
__device__ double g_psum_t[NSLOT][KTAIL], g_pssq_t[NSLOT][KTAIL];
__device__ double g_p2s_h[REDB][KHEAD], g_p2q_h[REDB][KHEAD];
__device__ double g_p2s_t[REDB][KTAIL], g_p2q_t[REDB][KTAIL];
__device__ double g_meand_h[KHEAD], g_ad_h[KHEAD];
__device__ double g_meand_t[KTAIL], g_ad_t[KTAIL];
__device__ int    g_wcnt;            // borderline-decision worklist
__device__ int    g_wlist[NDEC];

// ---------------- packed f32x2 helpers ----------------
__device__ __forceinline__ ull pack2(float lo, float hi) {
    ull r; asm("mov.b64 %0, {%1,%2};" : "=l"(r) : "f"(lo), "f"(hi)); return r;
}
__device__ __forceinline__ void unpack2(ull v, float& lo, float& hi) {
    asm("mov.b64 {%0,%1}, %2;" : "=f"(lo), "=f"(hi) : "l"(v));
}
__device__ __forceinline__ ull add2(ull a, ull b) {
    ull r; asm("add.rn.f32x2 %0, %1, %2;" : "=l"(r) : "l"(a), "l"(b)); return r;
}
__device__ __forceinline__ ull mul2(ull a, ull b) {
    ull r; asm("mul.rn.f32x2 %0, %1, %2;" : "=l"(r) : "l"(a), "l"(b)); return r;
}
#define FMA2(acc, a, b) asm("fma.rn.f32x2 %0, %2, %3, %0;" : "+l"(acc) : "l"(acc), "l"(a), "l"(b))

// Branchless top-2 update: identical decisions to the if/else-if chain
// (strict >, sequential), but compiles to FMNMX/SEL — no BSSY/BSYNC.
__device__ __forceinline__ void top2_update(float s, int idx,
                                            float& best, float& second, int& bk) {
    float m = fminf(best, s);
    second = fmaxf(second, m);
    bk = (s > best) ? idx : bk;
    best = fmaxf(best, s);
}

// ---------------- deterministic compaction ----------------
__global__ void count_kernel(const int* __restrict__ part) {
    __shared__ int cnt;
    if (threadIdx.x == 0) cnt = 0;
    __syncthreads();
    int i = blockIdx.x * 256 + threadIdx.x;
    bool h = (part[i] == 0);
    unsigned hm = __ballot_sync(0xffffffffu, h);
    if ((threadIdx.x & 31) == 0) atomicAdd(&cnt, __popc(hm));
    __syncthreads();
    if (threadIdx.x == 0) g_blkcnt[blockIdx.x] = cnt;
}

__global__ void scan_kernel() {
    __shared__ int buf[CBLK];
    int t = threadIdx.x;
    buf[t] = g_blkcnt[t];
    __syncthreads();
    for (int off = 1; off < CBLK; off <<= 1) {
        int v = (t >= off) ? buf[t - off] : 0;
        __syncthreads();
        buf[t] += v;
        __syncthreads();
    }
    g_blkoff[t] = buf[t] - g_blkcnt[t];
    if (t == 0) g_wcnt = 0;
    if (t == CBLK - 1) {
        g_cnt_h = buf[t];
        g_cnt_t = N_TOK - buf[t];
    }
}

__global__ void scatter_kernel(const int* __restrict__ part) {
    __shared__ int wcnt[8];
    int t = threadIdx.x;
    int lane = t & 31, w = t >> 5;
    int i = blockIdx.x * 256 + t;
    bool h = (part[i] == 0);
    unsigned hm = __ballot_sync(0xffffffffu, h);
    if (lane == 0) wcnt[w] = __popc(hm);
    __syncthreads();
    int wbase = 0;
    #pragma unroll
    for (int k = 0; k < 8; k++) wbase += (k < w) ? wcnt[k] : 0;
    int hrank = wbase + __popc(hm & ((1u << lane) - 1u));
    int hblk = g_blkoff[blockIdx.x];
    if (h) {
        g_head_list[hblk + hrank] = i;
    } else {
        int trank = t - hrank;
        int tblk = blockIdx.x * 256 - hblk;
        g_tail_list[tblk + trank] = i;
    }
}

// ---------------- head stats: 2 pairs/thread, 2 d per block ----------------
// FROZEN fp32 BITS (round-6 pattern) — do not touch.
__device__ __forceinline__ void stats_head2(const int* __restrict__ inp,
                                            const float* __restrict__ emb,
                                            const float* __restrict__ cent,
                                            char* smraw) {
    if (blockIdx.y >= 4) return;              // uniform across block
    constexpr int G = 128;
    const int t = threadIdx.x;
    const int g = t >> 6;
    const int pt = t & 63;
    const int d = blockIdx.y * 2 + g;
    const int slot = d * SBLK + blockIdx.x;
    ull (*xbuf)[SUBD + 2] = reinterpret_cast<ull (*)[SUBD + 2]>(smraw) + (size_t)g * G;

    ull cA[SUBD], cB[SUBD];
    float nA0 = 0.f, nA1 = 0.f, nB0 = 0.f, nB1 = 0.f;
    {
        const float* pa0 = cent + ((size_t)d * KHEAD + pt) * SUBD;
        const float* pa1 = pa0 + 128 * SUBD;
        const float* pb0 = cent + ((size_t)d * KHEAD + pt + 64) * SUBD;
        const float* pb1 = pb0 + 128 * SUBD;
        #pragma unroll
        for (int s = 0; s < SUBD; s++) {
            float a = pa0[s], b = pa1[s];
            cA[s] = pack2(a, b);
            nA0 = __fadd_rn(nA0, __fmul_rn(a, a));
            nA1 = __fadd_rn(nA1, __fmul_rn(b, b));
            float c = pb0[s], e = pb1[s];
            cB[s] = pack2(c, e);
            nB0 = __fadd_rn(nB0, __fmul_rn(c, c));
            nB1 = __fadd_rn(nB1, __fmul_rn(e, e));
        }
    }
    const ull negn2A = pack2(-nA0, -nA1);
    const ull negn2B = pack2(-nB0, -nB1);
    const ull two2   = pack2(2.f, 2.f);

    const int cnt = g_cnt_h;
    const int* list = g_head_list;

    double dsA0 = 0, dsA1 = 0, dqA0 = 0, dqA1 = 0;
    double dsB0 = 0, dsB1 = 0, dqB0 = 0, dqB1 = 0;
    const int base = blockIdx.x * (STAGES * G);

    for (int st = 0; st < STAGES; ++st) {
        int sb = base + st * G;
        int nval = cnt - sb;
        if (nval <= 0) break;                 // uniform across block
        if (nval > G) nval = G;
        __syncthreads();
        #pragma unroll
        for (int rr = 0; rr < 2; rr++) {
            int row = pt + rr * 64;
            if (row < nval) {
                int tokr = list[sb + row];
                const float* xr = emb + (size_t)inp[tokr] * EMBD + d * SUBD;
                float n1 = 0.f;
                #pragma unroll
                for (int s = 0; s < SUBD; s++) {
                    float v = xr[s];
                    *((float2*)&xbuf[row][s]) = make_float2(v, v);
                    n1 = __fadd_rn(n1, __fmul_rn(v, v));
                }
                *((float2*)&xbuf[row][SUBD]) = make_float2(-n1, -n1);
            }
        }
        __syncthreads();

        ull sumA = 0ull, ssqA = 0ull, sumB = 0ull, ssqB = 0ull;
        for (int j = 0; j < nval; j++) {
            const ulonglong2* xr2 = (const ulonglong2*)&xbuf[j][0];
            ull a0 = 0ull, a1 = 0ull, a2 = 0ull, a3 = 0ull;
            ull b0 = 0ull, b1 = 0ull, b2 = 0ull, b3 = 0ull;
            #pragma unroll
            for (int q = 0; q < SUBD / 4; q++) {
                ulonglong2 xA = xr2[2 * q];        // scalars 4q, 4q+1
                ulonglong2 xB = xr2[2 * q + 1];    // scalars 4q+2, 4q+3
                FMA2(a0, xA.x, cA[4 * q]);
                FMA2(a1, xA.y, cA[4 * q + 1]);
                FMA2(a2, xB.x, cA[4 * q + 2]);
                FMA2(a3, xB.y, cA[4 * q + 3]);
                FMA2(b0, xA.x, cB[4 * q]);
                FMA2(b1, xA.y, cB[4 * q + 1]);
                FMA2(b2, xB.x, cB[4 * q + 2]);
                FMA2(b3, xB.y, cB[4 * q + 3]);
            }
            ull xn1 = xbuf[j][SUBD];
            ull dotA = add2(add2(a0, a1), add2(a2, a3));
            ull rA = mul2(dotA, two2);             // round-6 epilogue order
            rA = add2(rA, xn1);
            rA = add2(rA, negn2A);
            sumA = add2(sumA, rA);
            FMA2(ssqA, rA, rA);
            ull dotB = add2(add2(b0, b1), add2(b2, b3));
            ull rB = mul2(dotB, two2);
            rB = add2(rB, xn1);
            rB = add2(rB, negn2B);
            sumB = add2(sumB, rB);
            FMA2(ssqB, rB, rB);
        }
        float s0, s1, q0, q1;
        unpack2(sumA, s0, s1); unpack2(ssqA, q0, q1);
        dsA0 += (double)s0; dsA1 += (double)s1;
        dqA0 += (double)q0; dqA1 += (double)q1;
        unpack2(sumB, s0, s1); unpack2(ssqB, q0, q1);
        dsB0 += (double)s0; dsB1 += (double)s1;
        dqB0 += (double)q0; dqB1 += (double)q1;
    }

    g_psum_h[slot][pt]       = dsA0;
    g_psum_h[slot][pt + 128] = dsA1;
    g_psum_h[slot][pt + 64]  = dsB0;
    g_psum_h[slot][pt + 192] = dsB1;
    g_pssq_h[slot][pt]       = dqA0;
    g_pssq_h[slot][pt + 128] = dqA1;
    g_pssq_h[slot][pt + 64]  = dqB0;
    g_pssq_h[slot][pt + 192] = dqB1;
}

// ---------------- tail stats (unchanged round-6 structure, frozen) ----------
__device__ __forceinline__ void stats_tail(const int* __restrict__ inp,
                                           const float* __restrict__ emb,
                                           const float* __restrict__ cent,
                                           char* sm) {
    constexpr int NK = KTAIL;
    constexpr int NP = NK / 2;
    constexpr int G = 128;
    const int t = threadIdx.x;
    const int d = blockIdx.y;
    const int slot = d * SBLK + blockIdx.x;
    const int pairid = t & 31;
    const int rep = t >> 5;
    const int nrep = 4;

    ull (*xbuf)[SUBD + 2] = reinterpret_cast<ull (*)[SUBD + 2]>(sm);

    ull c2[SUBD];
    float n20 = 0.f, n21 = 0.f;
    {
        const float* p0 = cent + ((size_t)d * KHEAD + pairid) * SUBD;
        const float* p1 = p0 + (size_t)NP * SUBD;
        #pragma unroll
        for (int s = 0; s < SUBD; s++) {
            float a = p0[s], b = p1[s];
            c2[s] = pack2(a, b);
            n20 = __fadd_rn(n20, __fmul_rn(a, a));
            n21 = __fadd_rn(n21, __fmul_rn(b, b));
        }
    }
    const ull negn22 = pack2(-n20, -n21);
    const ull two2   = pack2(2.f, 2.f);

    const int cnt = g_cnt_t;
    const int* list = g_tail_list;

    double dsum0 = 0, dsum1 = 0, dssq0 = 0, dssq1 = 0;
    const int base = blockIdx.x * (STAGES * G);

    for (int st = 0; st < STAGES; ++st) {
        int sb = base + st * G;
        int nval = cnt - sb;
        if (nval <= 0) break;
        if (nval > G) nval = G;
        __syncthreads();
        if (t < nval) {
            int tok = list[sb + t];
            const float* xr = emb + (size_t)inp[tok] * EMBD + d * SUBD;
            float n1 = 0.f;
            #pragma unroll
            for (int s = 0; s < SUBD; s++) {
                float v = xr[s];
                *((float2*)&xbuf[t][s]) = make_float2(v, v);
                n1 = __fadd_rn(n1, __fmul_rn(v, v));
            }
            *((float2*)&xbuf[t][SUBD]) = make_float2(-n1, -n1);
        }
        __syncthreads();

        ull sum2 = 0ull, ssq2 = 0ull;
        for (int j = rep; j < nval; j += nrep) {
            const ulonglong2* xr2 = (const ulonglong2*)&xbuf[j][0];
            ull a0 = 0ull, a1 = 0ull, a2r = 0ull, a3 = 0ull;
            #pragma unroll
            for (int q = 0; q < SUBD / 4; q++) {
                ulonglong2 xA = xr2[2 * q];
                ulonglong2 xB = xr2[2 * q + 1];
                FMA2(a0,  xA.x, c2[4 * q]);
                FMA2(a1,  xA.y, c2[4 * q + 1]);
                FMA2(a2r, xB.x, c2[4 * q + 2]);
                FMA2(a3,  xB.y, c2[4 * q + 3]);
            }
            ull dot2 = add2(add2(a0, a1), add2(a2r, a3));
            ull r2 = mul2(dot2, two2);
            r2 = add2(r2, xbuf[j][SUBD]);
            r2 = add2(r2, negn22);
            sum2 = add2(sum2, r2);
            FMA2(ssq2, r2, r2);
        }
        float s0, s1, q0, q1;
        unpack2(sum2, s0, s1); unpack2(ssq2, q0, q1);
        dsum0 += (double)s0; dsum1 += (double)s1;
        dssq0 += (double)q0; dssq1 += (double)q1;
    }

    __syncthreads();
    double (*red)[4] = reinterpret_cast<double (*)[4]>(sm);
    red[t][0] = dsum0; red[t][1] = dsum1; red[t][2] = dssq0; red[t][3] = dssq1;
    __syncthreads();
    if (t < 32) {
        double r0 = 0, r1 = 0, r2d = 0, r3 = 0;
        #pragma unroll
        for (int r = 0; r < 4; r++) {
            r0  += red[t + 32 * r][0];
            r1  += red[t + 32 * r][1];
            r2d += red[t + 32 * r][2];
            r3  += red[t + 32 * r][3];
        }
        g_psum_t[slot][t]      = r0;
        g_psum_t[slot][t + 32] = r1;
        g_pssq_t[slot][t]      = r2d;
        g_pssq_t[slot][t + 32] = r3;
    }
}

__global__ __launch_bounds__(128) void stats_merged(const int* __restrict__ inp,
                                                    const float* __restrict__ emb,
                                                    const float* __restrict__ cent) {
    __shared__ __align__(16) char sm[STATS_SMEM];
    if (blockIdx.z == 0) stats_head2(inp, emb, cent, sm);
    else                 stats_tail(inp, emb, cent, sm);
}

// ---------------- two-stage deterministic slot reduce ----------------
__global__ void reduce_kernel() {
    int b = blockIdx.x, t = threadIdx.x;
    double s = 0.0, q = 0.0;
    for (int i = 0; i < SPB; i++) {
        s += g_psum_h[b * SPB + i][t];
        q += g_pssq_h[b * SPB + i][t];
    }
    g_p2s_h[b][t] = s; g_p2q_h[b][t] = q;
    if (t < KTAIL) {
        double s2 = 0.0, q2 = 0.0;
        for (int i = 0; i < SPB; i++) {
            s2 += g_psum_t[b * SPB + i][t];
            q2 += g_pssq_t[b * SPB + i][t];
        }
        g_p2s_t[b][t] = s2; g_p2q_t[b][t] = q2;
    }
}

__global__ void finalize_kernel() {
    int t = threadIdx.x;
    if (t < KHEAD) {
        double s = 0.0, q = 0.0;
        for (int i = 0; i < REDB; i++) { s += g_p2s_h[i][t]; q += g_p2q_h[i][t]; }
        double cnt = (double)g_cnt_h * 8.0; if (cnt < 1.0) cnt = 1.0;
        double m = s / cnt;
        double v = q / cnt - m * m;
        float vf = (float)v; if (!(vf > 0.f)) vf = 0.f;
        g_meand_h[t] = m;
        g_ad_h[t] = 1.0 / sqrt((double)(vf + 0.001f));
    } else if (t < KHEAD + KTAIL) {
        int k = t - KHEAD;
        double s = 0.0, q = 0.0;
        for (int i = 0; i < REDB; i++) { s += g_p2s_t[i][k]; q += g_p2q_t[i][k]; }
        double cnt = (double)g_cnt_t * 8.0; if (cnt < 1.0) cnt = 1.0;
        double m = s / cnt;
        double v = q / cnt - m * m;
        float vf = (float)v; if (!(vf > 0.f)) vf = 0.f;
        g_meand_t[k] = m;
        g_ad_t[k] = 1.0 / sqrt((double)(vf + 0.001f));
    }
}

// ---------------- argmax hot kernel (2 tokens/thread, branchless top-2) ----
// Borderline decisions (margin <= TAU) go to the exact fixup kernel.
template<int NK>
__device__ __forceinline__ void argmax_body(const int* __restrict__ inp,
                                            const float* __restrict__ emb,
                                            const float* __restrict__ cent,
                                            float* __restrict__ out,
                                            char* sm) {
    constexpr int NP = NK / 2;
    const int d = blockIdx.y;
    ull (*c2s)[SUBD] = reinterpret_cast<ull (*)[SUBD]>(sm);
    ull (*cst)[4]    = reinterpret_cast<ull (*)[4]>(sm + (size_t)NP * SUBD * 8);

    const double* meand = (NK == 256) ? g_meand_h : g_meand_t;
    const double* ad    = (NK == 256) ? g_ad_h    : g_ad_t;

    for (int j = threadIdx.x; j < NP; j += blockDim.x) {
        const float* p0 = cent + ((size_t)d * KHEAD + j) * SUBD;
        const float* p1 = p0 + (size_t)NP * SUBD;
        double n2d0 = 0.0, n2d1 = 0.0;
        #pragma unroll
        for (int s = 0; s < SUBD; s++) {
            float a = p0[s], b = p1[s];
            c2s[j][s] = pack2(a, b);
            n2d0 += (double)a * (double)a;
            n2d1 += (double)b * (double)b;
        }
        double a0 = ad[j], a1 = ad[j + NP];
        float af0 = (float)a0, af1 = (float)a1;
        float e0 = (float)(-(n2d0 + meand[j]) * a0);
        float e1 = (float)(-(n2d1 + meand[j + NP]) * a1);
        cst[j][0] = pack2(2.f * af0, 2.f * af1);
        cst[j][1] = pack2(af0, af1);
        cst[j][2] = pack2(e0, e1);
    }
    __syncthreads();

    const int cnt = (NK == 256) ? g_cnt_h : g_cnt_t;
    const int* list = (NK == 256) ? g_head_list : g_tail_list;
    int ibase = (blockIdx.x * blockDim.x + threadIdx.x) * 2;
    if (ibase >= cnt) return;
    const int ntk = (ibase + 1 < cnt) ? 2 : 1;

    int tok[2];
    tok[0] = list[ibase];
    tok[1] = (ntk == 2) ? list[ibase + 1] : tok[0];
    ull xd[2][SUBD], negn1[2];
    #pragma unroll
    for (int u = 0; u < 2; u++) {
        const float* xr = emb + (size_t)inp[tok[u]] * EMBD + d * SUBD;
        float n1 = 0.f;
        #pragma unroll
        for (int s = 0; s < SUBD; s++) {
            float v = xr[s];
            n1 = __fadd_rn(n1, __fmul_rn(v, v));
            xd[u][s] = pack2(v, v);
        }
        negn1[u] = pack2(-n1, -n1);
    }

    float best[2] = {-3.4e38f, -3.4e38f};
    float second[2] = {-3.4e38f, -3.4e38f};
    int bk[2] = {0, 0};
    for (int j = 0; j < NP; j++) {
        const ulonglong2* crow = (const ulonglong2*)&c2s[j][0];
        ulonglong2 kc = ((const ulonglong2*)&cst[j][0])[0];   // (twoa2, a2)
        ull e2 = cst[j][2];
        ull a0 = 0ull, a1 = 0ull, b0 = 0ull, b1 = 0ull;
        #pragma unroll
        for (int q = 0; q < SUBD / 2; q++) {
            ulonglong2 cA = crow[q];
            FMA2(a0, xd[0][2 * q],     cA.x);
            FMA2(a1, xd[0][2 * q + 1], cA.y);
            FMA2(b0, xd[1][2 * q],     cA.x);
            FMA2(b1, xd[1][2 * q + 1], cA.y);
        }
        ull dA = add2(a0, a1);
        ull tA = e2;
        FMA2(tA, kc.y, negn1[0]);
        FMA2(tA, kc.x, dA);
        ull dB = add2(b0, b1);
        ull tB = e2;
        FMA2(tB, kc.y, negn1[1]);
        FMA2(tB, kc.x, dB);
        float s0, s1;
        unpack2(tA, s0, s1);
        top2_update(s0, j,      best[0], second[0], bk[0]);
        top2_update(s1, j + NP, best[0], second[0], bk[0]);
        unpack2(tB, s0, s1);
        top2_update(s0, j,      best[1], second[1], bk[1]);
        top2_update(s1, j + NP, best[1], second[1], bk[1]);
    }

    #pragma unroll
    for (int u = 0; u < 2; u++) {
        if (u < ntk) {
            // Borderline -> defer exact decision to fixup kernel
            if (best[u] - second[u] <= TAU) {
                int w = atomicAdd(&g_wcnt, 1);
                g_wlist[w] = (tok[u] << 4) | (d << 1) | ((NK == 256) ? 0 : 1);
            }
            int jj = (bk[u] < NP) ? bk[u] : (bk[u] - NP);
            bool hi_half = (bk[u] >= NP);
            float ov[SUBD];
            #pragma unroll
            for (int s = 0; s < SUBD; s++) {
                float lo, hf; unpack2(c2s[jj][s], lo, hf);
                float cv = hi_half ? hf : lo;
                float xlo, xhi; unpack2(xd[u][s], xlo, xhi);
                ov[s] = __fadd_rn(__fsub_rn(cv, xlo), xlo);  // straight-through
            }
            float4* op = (float4*)(out + (size_t)tok[u] * EMBD + d * SUBD);
            #pragma unroll
            for (int q = 0; q < 4; q++)
                op[q] = make_float4(ov[4 * q], ov[4 * q + 1], ov[4 * q + 2], ov[4 * q + 3]);
        }
    }
}

// merged launch: z=0 -> head, z=1 -> tail
__global__ __launch_bounds__(128) void argmax_merged(const int* __restrict__ inp,
                                                     const float* __restrict__ emb,
                                                     const float* __restrict__ cent,
                                                     float* __restrict__ out) {
    __shared__ __align__(16) char sm[ARGMX_SMEM];
    if (blockIdx.z == 0) argmax_body<KHEAD>(inp, emb, cent, out, sm);
    else                 argmax_body<KTAIL>(inp, emb, cent, out, sm);
}

// ---------------- exact fixup (bit-identical to the frozen slow path) ------
__global__ void fixup_kernel(const int* __restrict__ inp,
                             const float* __restrict__ emb,
                             const float* __restrict__ cent,
                             float* __restrict__ out) {
    int total = g_wcnt;
    for (int w = blockIdx.x * blockDim.x + threadIdx.x; w < total;
         w += gridDim.x * blockDim.x) {
        int e = g_wlist[w];
        int tok = e >> 4;
        int d = (e >> 1) & 7;
        int tail = e & 1;
        int NK = tail ? KTAIL : KHEAD;
        const double* meand = tail ? g_meand_t : g_meand_h;
        const double* ad    = tail ? g_ad_t    : g_ad_h;

        const float* xr = emb + (size_t)inp[tok] * EMBD + d * SUBD;
        float xs[SUBD];
        double n1d = 0.0;
        #pragma unroll
        for (int s = 0; s < SUBD; s++) {
            xs[s] = xr[s];
            n1d += (double)xs[s] * (double)xs[s];
        }
        const float* cd = cent + (size_t)d * KHEAD * SUBD;
        double bestd = -1e300; int bk = 0;
        for (int k = 0; k < NK; k++) {
            const float* cp = cd + k * SUBD;
            double dot = 0.0, n2 = 0.0;
            #pragma unroll
            for (int s = 0; s < SUBD; s++) {
                double cv = (double)cp[s];
                dot += (double)xs[s] * cv;
                n2  += cv * cv;
            }
            double r = -n1d + 2.0 * dot - n2;
            double v = (r - meand[k]) * ad[k];
            if (v > bestd) { bestd = v; bk = k; }
        }

        const float* cp = cd + bk * SUBD;
        float ov[SUBD];
        #pragma unroll
        for (int s = 0; s < SUBD; s++)
            ov[s] = __fadd_rn(__fsub_rn(cp[s], xs[s]), xs[s]);
        float4* op = (float4*)(out + (size_t)tok * EMBD + d * SUBD);
        #pragma unroll
        for (int q = 0; q < 4; q++)
            op[q] = make_float4(ov[4 * q], ov[4 * q + 1], ov[4 * q + 2], ov[4 * q + 3]);
    }
}

// ---------------- launch ----------------
extern "C" void kernel_launch(void* const* d_in, const int* in_sizes, int n_in,
                              void* d_out, int out_size) {
    const int*   inp  = (const int*)d_in[0];    // inputs (1024,64) int32
    const int*   part = (const int*)d_in[1];    // partitions (65536,) int32
    const float* emb  = (const float*)d_in[2];  // emb_table (100000,128) f32
    const float* cent = (const float*)d_in[3];  // centroids (8,256,16) f32
    float* out = (float*)d_out;

    count_kernel<<<CBLK, 256>>>(part);
    scan_kernel<<<1, 256>>>();                  // also zeroes g_wcnt
    scatter_kernel<<<CBLK, 256>>>(part);

    // z=0: head (y<4 used, 2 d per block); z=1: tail (y 0..7)
    stats_merged<<<dim3(SBLK, DSUB, 2), 128>>>(inp, emb, cent);

    reduce_kernel<<<REDB, 256>>>();
    finalize_kernel<<<1, 384>>>();

    // 2 tokens per thread: 256 x-blocks * 128 thr * 2 = 65536 worst-case
    argmax_merged<<<dim3(256, DSUB, 2), 128>>>(inp, emb, cent, out);
    fixup_kernel<<<128, 128>>>(inp, emb, cent, out);
}